// round 14
// baseline (speedup 1.0000x reference)
#include <cuda_runtime.h>
#include <cuda_fp16.h>
#include <cstdint>

// Problem constants
#define NE 16
#define NH 2048
#define NI 1408
#define NK 2
#define NT 8192
#define CAP (NT * NK)   // 16384 routed slots

// ---------------- scratch (device globals; no cudaMalloc allowed) ----------
__device__ int   g_offsets[NE + 1];
__device__ int   g_slot_token[CAP];
__device__ float g_slot_w[CAP];
__device__ int   g_ntiles;
__device__ int   g_tile_e[160];
__device__ int   g_tile_m0[160];

// fp16 operands (round-to-nearest from fp32)
__device__ __align__(16) __half g_hid_h[(size_t)NT * NH];
__device__ __align__(16) __half g_wgu_h[(size_t)NE * 2 * NI * NH];
__device__ __align__(16) __half g_wdn_h[(size_t)NE * NH * NI];
__device__ __align__(16) __half g_h_h[(size_t)CAP * NI];

// ---------------- PTX helpers (baseline ISA only: sm_80+ features) ---------
__device__ __forceinline__ uint32_t smem_u32(const void* p) {
    uint32_t a;
    asm("{ .reg .u64 t; cvta.to.shared.u64 t, %1; cvt.u32.u64 %0, t; }" : "=r"(a) : "l"(p));
    return a;
}
#define CP_ASYNC16(dst, src) \
    asm volatile("cp.async.cg.shared.global [%0], [%1], 16;" :: "r"(dst), "l"(src))
#define CP_COMMIT() asm volatile("cp.async.commit_group;" ::: "memory")
#define CP_WAIT(N)  asm volatile("cp.async.wait_group %0;" :: "n"(N) : "memory")

#define LDSM4(r, addr) \
    asm volatile("ldmatrix.sync.aligned.m8n8.x4.shared.b16 {%0,%1,%2,%3}, [%4];" \
        : "=r"((r)[0]), "=r"((r)[1]), "=r"((r)[2]), "=r"((r)[3]) : "r"(addr))

#define MMA16816(c, a, b0_, b1_) \
    asm volatile("mma.sync.aligned.m16n8k16.row.col.f32.f16.f16.f32 " \
        "{%0,%1,%2,%3}, {%4,%5,%6,%7}, {%8,%9}, {%0,%1,%2,%3};" \
        : "+f"((c)[0]), "+f"((c)[1]), "+f"((c)[2]), "+f"((c)[3]) \
        : "r"((a)[0]), "r"((a)[1]), "r"((a)[2]), "r"((a)[3]), "r"(b0_), "r"(b1_))

// ---------------- prep: routing + all conversions + out zero, one kernel ---
#define PREP_HID_BLKS 2048
#define PREP_WGU_BLKS 8192
#define PREP_WDN_BLKS 4096
#define PREP_OUT_BLKS 1024
#define PREP_BLKS (1 + PREP_HID_BLKS + PREP_WGU_BLKS + PREP_WDN_BLKS + PREP_OUT_BLKS)

__global__ void k_prep(const float4* __restrict__ hidden,
                       const int*    __restrict__ idx32,
                       const float*  __restrict__ w,
                       const float4* __restrict__ wgu,
                       const float4* __restrict__ wdn,
                       float4*       __restrict__ out) {
    const int bid = blockIdx.x;
    const int tid = threadIdx.x;
    if (bid == 0) {
        // ---- routing ----
        __shared__ int cnt[NE], base_[NE], fill[NE];
        __shared__ int is64_s;
        if (tid < NE) { cnt[tid] = 0; fill[tid] = 0; }
        if (tid == 0) is64_s = 1;
        __syncthreads();
        // dtype detect: JAX x64-off silently downgrades int64->int32.
        if (tid < 256) {
            int lo = idx32[2 * tid], hi = idx32[2 * tid + 1];
            if (hi != 0 || lo < 0 || lo >= NE) atomicExch(&is64_s, 0);
        }
        __syncthreads();
        const int is64 = is64_s;
        for (int s = tid; s < CAP; s += blockDim.x) {
            int e = is64 ? (int)((const long long*)idx32)[s] : idx32[s];
            if (e >= 0 && e < NE) atomicAdd(&cnt[e], 1);
        }
        __syncthreads();
        if (tid == 0) {
            int acc = 0, nt = 0;
            for (int e = 0; e < NE; e++) {
                base_[e] = acc; g_offsets[e] = acc;
                for (int m0 = 0; m0 < cnt[e]; m0 += 128) {
                    g_tile_e[nt] = e; g_tile_m0[nt] = m0; nt++;
                }
                acc += cnt[e];
            }
            g_offsets[NE] = acc;
            g_ntiles = nt;
        }
        __syncthreads();
        for (int s = tid; s < CAP; s += blockDim.x) {
            int e = is64 ? (int)((const long long*)idx32)[s] : idx32[s];
            if (e >= 0 && e < NE) {
                int p = base_[e] + atomicAdd(&fill[e], 1);
                g_slot_token[p] = s / NK;
                g_slot_w[p]     = w[s];
            }
        }
        return;
    }
    int b = bid - 1;
    if (b < PREP_HID_BLKS + PREP_WGU_BLKS + PREP_WDN_BLKS) {
        const float4* src; __half2* dst; size_t n4, i, stride;
        if (b < PREP_HID_BLKS) {
            src = hidden; dst = (__half2*)g_hid_h;
            n4 = (size_t)NT * NH / 4;
            i = (size_t)b * blockDim.x + tid;
            stride = (size_t)PREP_HID_BLKS * blockDim.x;
        } else if (b < PREP_HID_BLKS + PREP_WGU_BLKS) {
            src = wgu; dst = (__half2*)g_wgu_h;
            n4 = (size_t)NE * 2 * NI * NH / 4;
            i = (size_t)(b - PREP_HID_BLKS) * blockDim.x + tid;
            stride = (size_t)PREP_WGU_BLKS * blockDim.x;
        } else {
            src = wdn; dst = (__half2*)g_wdn_h;
            n4 = (size_t)NE * NH * NI / 4;
            i = (size_t)(b - PREP_HID_BLKS - PREP_WGU_BLKS) * blockDim.x + tid;
            stride = (size_t)PREP_WDN_BLKS * blockDim.x;
        }
        for (; i < n4; i += stride) {
            float4 v = src[i];
            dst[2 * i]     = __halves2half2(__float2half(v.x), __float2half(v.y));
            dst[2 * i + 1] = __halves2half2(__float2half(v.z), __float2half(v.w));
        }
    } else {
        b -= PREP_HID_BLKS + PREP_WGU_BLKS + PREP_WDN_BLKS;
        const size_t o4 = (size_t)NT * NH / 4;
        float4 z = make_float4(0.f, 0.f, 0.f, 0.f);
        size_t i = (size_t)b * blockDim.x + tid;
        size_t stride = (size_t)PREP_OUT_BLKS * blockDim.x;
        for (; i < o4; i += stride) out[i] = z;
    }
}

// ---------------- HMMA GEMMs ----------------
// M-tile 128 x N-tile 128, K-chunks of 64, 3 CTAs/SM, 2-stage cp.async
// pipeline (two barriers per chunk; occ-3 hides the barrier cost).
// Warps in 4x2 grid: warp tile 32 rows x 64 cols.
#define ROW_B   144
#define A_TB    (128 * ROW_B)               // 18432 B
#define B_TB    (128 * ROW_B)               // 18432 B
#define STAGE_B (A_TB + B_TB)               // 36864 B
#define NSTAGE  2
#define SMEM_TOT (NSTAGE * STAGE_B)         // 73728 B
#define OFF_A  0
#define OFF_B  A_TB
#define MAX_TILES 144

// ---- GEMM1: C[128 slots, 64 channels as gate|up pairs], K = NH ----
__global__ __launch_bounds__(256, 3) void k_gemm1() {
    extern __shared__ char smem[];
    const int ty = blockIdx.y;
    if (ty >= g_ntiles) return;
    const int e     = g_tile_e[ty];
    const int m0    = g_tile_m0[ty];
    const int start = g_offsets[e];
    const int M     = g_offsets[e + 1] - start;
    const int i0 = blockIdx.x * 64;     // gridDim.x = NI/64 = 22

    const int tid    = threadIdx.x;
    const int wid    = tid >> 5;
    const int lane   = tid & 31;
    const int warp_m = wid >> 1;        // 0..3
    const int warp_n = wid & 1;         // 0..1
    uint32_t sb = smem_u32(smem);

    const int vrow = tid >> 3;          // 0..31
    const int col8 = tid & 7;
    uint32_t arow[4], brow[4];          // element offsets (fit in u32)
#pragma unroll
    for (int i = 0; i < 4; i++) {
        int row = vrow + 32 * i;        // 0..127
        int ar  = m0 + row; if (ar >= M) ar = M - 1;
        arow[i] = (uint32_t)g_slot_token[start + ar] * NH;
        int half_ = row >> 6;
        int local = row & 63;
        int ch    = i0 + half_ * 32 + (local & 31);
        int role  = (local >> 5) & 1;
        brow[i] = (uint32_t)e * (2 * NI * NH) + (uint32_t)(ch + role * NI) * NH;
    }

    auto issue = [&](int s, int kk) {
        uint32_t base = sb + s * STAGE_B;
#pragma unroll
        for (int i = 0; i < 4; i++) {
            int row = vrow + 32 * i;
            uint32_t d = base + row * ROW_B + col8 * 16;
            CP_ASYNC16(d + OFF_A, g_hid_h + arow[i] + kk + col8 * 8);
            CP_ASYNC16(d + OFF_B, g_wgu_h + brow[i] + kk + col8 * 8);
        }
    };

    float acc[2][8][4];
#pragma unroll
    for (int mf = 0; mf < 2; mf++)
#pragma unroll
        for (int q = 0; q < 8; q++)
#pragma unroll
            for (int i = 0; i < 4; i++) acc[mf][q][i] = 0.f;

    const uint32_t a_base = (uint32_t)((warp_m * 32 + (lane & 15)) * ROW_B + (lane >> 4) * 16);
    const uint32_t b_base = (uint32_t)((warp_n * 64 + (lane & 7) + ((lane >> 4) & 1) * 8) * ROW_B +
                                       ((lane >> 3) & 1) * 16);

    issue(0, 0);
    CP_COMMIT();

    const int NCH = NH / 64;
    for (int c = 0; c < NCH; c++) {
        if (c + 1 < NCH) { issue((c + 1) & 1, (c + 1) * 64); CP_COMMIT(); CP_WAIT(1); }
        else             { CP_WAIT(0); }
        __syncthreads();
        uint32_t base = sb + (c & 1) * STAGE_B;
#pragma unroll
        for (int kk = 0; kk < 4; kk++) {
            uint32_t a0[4], a1[4];
            LDSM4(a0, base + OFF_A + a_base + kk * 32);
            LDSM4(a1, base + OFF_A + a_base + 16 * ROW_B + kk * 32);
#pragma unroll
            for (int nt = 0; nt < 4; nt++) {
                uint32_t bh[4];
                uint32_t bo = b_base + nt * (16 * ROW_B) + kk * 32;
                LDSM4(bh, base + OFF_B + bo);
                MMA16816(acc[0][2 * nt],     a0, bh[0], bh[1]);
                MMA16816(acc[0][2 * nt + 1], a0, bh[2], bh[3]);
                MMA16816(acc[1][2 * nt],     a1, bh[0], bh[1]);
                MMA16816(acc[1][2 * nt + 1], a1, bh[2], bh[3]);
            }
        }
        __syncthreads();
    }

    // epilogue: acc[.][q] (q<4) = gate, acc[.][q+4] = up; h = silu(g)*u
    const int cb = (lane & 3) * 2;
#pragma unroll
    for (int mf = 0; mf < 2; mf++) {
        int rbase = m0 + warp_m * 32 + mf * 16 + (lane >> 2);
#pragma unroll
        for (int q = 0; q < 4; q++) {
            int ch = i0 + warp_n * 32 + q * 8 + cb;
#pragma unroll
            for (int half = 0; half < 2; half++) {
                int row = rbase + half * 8;
                if (row >= M) continue;
                float g0 = acc[mf][q][2 * half + 0],     g1 = acc[mf][q][2 * half + 1];
                float u0 = acc[mf][q + 4][2 * half + 0], u1 = acc[mf][q + 4][2 * half + 1];
                float h0 = u0 * g0 / (1.f + __expf(-g0));
                float h1 = u1 * g1 / (1.f + __expf(-g1));
                size_t o = (size_t)(start + row) * NI + ch;
                *(__half2*)(g_h_h + o) =
                    __halves2half2(__float2half(h0), __float2half(h1));
            }
        }
    }
}

// ---- GEMM2: C[128 slots, 128 hidden], K = NI; weighted atomic scatter ----
__global__ __launch_bounds__(256, 3) void k_gemm2(float* __restrict__ out) {
    extern __shared__ char smem[];
    const int ty = blockIdx.y;
    if (ty >= g_ntiles) return;
    const int e     = g_tile_e[ty];
    const int m0    = g_tile_m0[ty];
    const int start = g_offsets[e];
    const int M     = g_offsets[e + 1] - start;
    const int n0 = blockIdx.x * 128;    // gridDim.x = NH/128 = 16

    const int tid    = threadIdx.x;
    const int wid    = tid >> 5;
    const int lane   = tid & 31;
    const int warp_m = wid >> 1;
    const int warp_n = wid & 1;
    uint32_t sb = smem_u32(smem);

    const int vrow = tid >> 3;
    const int col8 = tid & 7;
    uint32_t arow[4], brow[4];
#pragma unroll
    for (int i = 0; i < 4; i++) {
        int row = vrow + 32 * i;
        int ar  = m0 + row; if (ar >= M) ar = M - 1;
        arow[i] = (uint32_t)(start + ar) * NI;
        brow[i] = (uint32_t)e * (NH * NI) + (uint32_t)(n0 + row) * NI;
    }

    auto issue = [&](int s, int kk) {
        uint32_t base = sb + s * STAGE_B;
#pragma unroll
        for (int i = 0; i < 4; i++) {
            int row = vrow + 32 * i;
            uint32_t d = base + row * ROW_B + col8 * 16;
            CP_ASYNC16(d + OFF_A, g_h_h   + arow[i] + kk + col8 * 8);
            CP_ASYNC16(d + OFF_B, g_wdn_h + brow[i] + kk + col8 * 8);
        }
    };

    float acc[2][8][4];
#pragma unroll
    for (int mf = 0; mf < 2; mf++)
#pragma unroll
        for (int q = 0; q < 8; q++)
#pragma unroll
            for (int i = 0; i < 4; i++) acc[mf][q][i] = 0.f;

    const uint32_t a_base = (uint32_t)((warp_m * 32 + (lane & 15)) * ROW_B + (lane >> 4) * 16);
    const uint32_t b_base = (uint32_t)((warp_n * 64 + (lane & 7) + ((lane >> 4) & 1) * 8) * ROW_B +
                                       ((lane >> 3) & 1) * 16);

    issue(0, 0);
    CP_COMMIT();

    const int NCH = NI / 64;
    for (int c = 0; c < NCH; c++) {
        if (c + 1 < NCH) { issue((c + 1) & 1, (c + 1) * 64); CP_COMMIT(); CP_WAIT(1); }
        else             { CP_WAIT(0); }
        __syncthreads();
        uint32_t base = sb + (c & 1) * STAGE_B;
#pragma unroll
        for (int kk = 0; kk < 4; kk++) {
            uint32_t a0[4], a1[4];
            LDSM4(a0, base + OFF_A + a_base + kk * 32);
            LDSM4(a1, base + OFF_A + a_base + 16 * ROW_B + kk * 32);
#pragma unroll
            for (int nt = 0; nt < 4; nt++) {
                uint32_t bh[4];
                uint32_t bo = b_base + nt * (16 * ROW_B) + kk * 32;
                LDSM4(bh, base + OFF_B + bo);
                MMA16816(acc[0][2 * nt],     a0, bh[0], bh[1]);
                MMA16816(acc[0][2 * nt + 1], a0, bh[2], bh[3]);
                MMA16816(acc[1][2 * nt],     a1, bh[0], bh[1]);
                MMA16816(acc[1][2 * nt + 1], a1, bh[2], bh[3]);
            }
        }
        __syncthreads();
    }

    // epilogue: out[tok, n0 + warp_n*64 + col] += w * acc
    const int cb = (lane & 3) * 2;
#pragma unroll
    for (int mf = 0; mf < 2; mf++) {
        int rbase = m0 + warp_m * 32 + mf * 16 + (lane >> 2);
#pragma unroll
        for (int half = 0; half < 2; half++) {
            int row = rbase + half * 8;
            if (row >= M) continue;
            int   tok = g_slot_token[start + row];
            float w   = g_slot_w[start + row];
            float* orow = out + (size_t)tok * NH + n0 + warp_n * 64;
#pragma unroll
            for (int q = 0; q < 8; q++) {
                atomicAdd(orow + q * 8 + cb + 0, w * acc[mf][q][2 * half + 0]);
                atomicAdd(orow + q * 8 + cb + 1, w * acc[mf][q][2 * half + 1]);
            }
        }
    }
}

// ---------------- launch -----------------
extern "C" void kernel_launch(void* const* d_in, const int* in_sizes, int n_in,
                              void* d_out, int out_size) {
    const float* hidden = (const float*)d_in[0];   // [T, H]
    const void*  idx    = d_in[1];                 // [T, K] int32 or int64
    const float* wts    = (const float*)d_in[2];   // [T, K]
    const float* wgu    = (const float*)d_in[3];   // [E, 2I, H]
    const float* wdn    = (const float*)d_in[4];   // [E, H, I]
    (void)in_sizes; (void)n_in; (void)out_size;

    cudaFuncSetAttribute(k_gemm1, cudaFuncAttributeMaxDynamicSharedMemorySize, SMEM_TOT);
    cudaFuncSetAttribute(k_gemm2, cudaFuncAttributeMaxDynamicSharedMemorySize, SMEM_TOT);

    // prefix: routing + all fp16 conversions + output zero (one kernel)
    k_prep<<<PREP_BLKS, 256>>>((const float4*)hidden, (const int*)idx, wts,
                               (const float4*)wgu, (const float4*)wdn,
                               (float4*)d_out);

    // GEMM1: x = NI/64 = 22 tiles, y = compact tile list
    dim3 g1(NI / 64, MAX_TILES, 1);
    k_gemm1<<<g1, 256, SMEM_TOT>>>();

    // GEMM2: x = NH/128 = 16 tiles
    dim3 g2(NH / 128, MAX_TILES, 1);
    k_gemm2<<<g2, 256, SMEM_TOT>>>((float*)d_out);
}

// round 15
// speedup vs baseline: 1.8814x; 1.8814x over previous
#include <cuda_runtime.h>
#include <cuda_fp16.h>
#include <cstdint>

// Problem constants
#define NE 16
#define NH 2048
#define NI 1408
#define NK 2
#define NT 8192
#define CAP (NT * NK)   // 16384 routed slots

// ---------------- scratch (device globals; no cudaMalloc allowed) ----------
__device__ int   g_offsets[NE + 1];
__device__ int   g_slot_token[CAP];
__device__ float g_slot_w[CAP];
__device__ int   g_ntiles;
__device__ int   g_tile_e[160];
__device__ int   g_tile_m0[160];

// fp16 operands (round-to-nearest from fp32)
__device__ __align__(16) __half g_hid_h[(size_t)NT * NH];
__device__ __align__(16) __half g_wgu_h[(size_t)NE * 2 * NI * NH];
__device__ __align__(16) __half g_wdn_h[(size_t)NE * NH * NI];
__device__ __align__(16) __half g_h_h[(size_t)CAP * NI];

// ---------------- PTX helpers (baseline ISA only: sm_80+ features) ---------
__device__ __forceinline__ uint32_t smem_u32(const void* p) {
    uint32_t a;
    asm("{ .reg .u64 t; cvta.to.shared.u64 t, %1; cvt.u32.u64 %0, t; }" : "=r"(a) : "l"(p));
    return a;
}
#define CP_ASYNC16(dst, src) \
    asm volatile("cp.async.cg.shared.global [%0], [%1], 16;" :: "r"(dst), "l"(src))
#define CP_COMMIT() asm volatile("cp.async.commit_group;" ::: "memory")
#define CP_WAIT(N)  asm volatile("cp.async.wait_group %0;" :: "n"(N) : "memory")

#define LDSM4(r, addr) \
    asm volatile("ldmatrix.sync.aligned.m8n8.x4.shared.b16 {%0,%1,%2,%3}, [%4];" \
        : "=r"((r)[0]), "=r"((r)[1]), "=r"((r)[2]), "=r"((r)[3]) : "r"(addr))

#define MMA16816(c, a, b0_, b1_) \
    asm volatile("mma.sync.aligned.m16n8k16.row.col.f32.f16.f16.f32 " \
        "{%0,%1,%2,%3}, {%4,%5,%6,%7}, {%8,%9}, {%0,%1,%2,%3};" \
        : "+f"((c)[0]), "+f"((c)[1]), "+f"((c)[2]), "+f"((c)[3]) \
        : "r"((a)[0]), "r"((a)[1]), "r"((a)[2]), "r"((a)[3]), "r"(b0_), "r"(b1_))

// ---------------- prep: routing + all conversions + out zero, one kernel ---
#define PREP_HID_BLKS 2048
#define PREP_WGU_BLKS 8192
#define PREP_WDN_BLKS 4096
#define PREP_OUT_BLKS 1024
#define PREP_BLKS (1 + PREP_HID_BLKS + PREP_WGU_BLKS + PREP_WDN_BLKS + PREP_OUT_BLKS)

__global__ void k_prep(const float4* __restrict__ hidden,
                       const int*    __restrict__ idx32,
                       const float*  __restrict__ w,
                       const float4* __restrict__ wgu,
                       const float4* __restrict__ wdn,
                       float4*       __restrict__ out) {
    const int bid = blockIdx.x;
    const int tid = threadIdx.x;
    if (bid == 0) {
        // ---- routing ----
        __shared__ int cnt[NE], base_[NE], fill[NE];
        __shared__ int is64_s;
        if (tid < NE) { cnt[tid] = 0; fill[tid] = 0; }
        if (tid == 0) is64_s = 1;
        __syncthreads();
        // dtype detect: JAX x64-off silently downgrades int64->int32.
        if (tid < 256) {
            int lo = idx32[2 * tid], hi = idx32[2 * tid + 1];
            if (hi != 0 || lo < 0 || lo >= NE) atomicExch(&is64_s, 0);
        }
        __syncthreads();
        const int is64 = is64_s;
        for (int s = tid; s < CAP; s += blockDim.x) {
            int e = is64 ? (int)((const long long*)idx32)[s] : idx32[s];
            if (e >= 0 && e < NE) atomicAdd(&cnt[e], 1);
        }
        __syncthreads();
        if (tid == 0) {
            int acc = 0, nt = 0;
            for (int e = 0; e < NE; e++) {
                base_[e] = acc; g_offsets[e] = acc;
                for (int m0 = 0; m0 < cnt[e]; m0 += 128) {
                    g_tile_e[nt] = e; g_tile_m0[nt] = m0; nt++;
                }
                acc += cnt[e];
            }
            g_offsets[NE] = acc;
            g_ntiles = nt;
        }
        __syncthreads();
        for (int s = tid; s < CAP; s += blockDim.x) {
            int e = is64 ? (int)((const long long*)idx32)[s] : idx32[s];
            if (e >= 0 && e < NE) {
                int p = base_[e] + atomicAdd(&fill[e], 1);
                g_slot_token[p] = s / NK;
                g_slot_w[p]     = w[s];
            }
        }
        return;
    }
    int b = bid - 1;
    if (b < PREP_HID_BLKS + PREP_WGU_BLKS + PREP_WDN_BLKS) {
        const float4* src; __half2* dst; size_t n4, i, stride;
        if (b < PREP_HID_BLKS) {
            src = hidden; dst = (__half2*)g_hid_h;
            n4 = (size_t)NT * NH / 4;
            i = (size_t)b * blockDim.x + tid;
            stride = (size_t)PREP_HID_BLKS * blockDim.x;
        } else if (b < PREP_HID_BLKS + PREP_WGU_BLKS) {
            src = wgu; dst = (__half2*)g_wgu_h;
            n4 = (size_t)NE * 2 * NI * NH / 4;
            i = (size_t)(b - PREP_HID_BLKS) * blockDim.x + tid;
            stride = (size_t)PREP_WGU_BLKS * blockDim.x;
        } else {
            src = wdn; dst = (__half2*)g_wdn_h;
            n4 = (size_t)NE * NH * NI / 4;
            i = (size_t)(b - PREP_HID_BLKS - PREP_WGU_BLKS) * blockDim.x + tid;
            stride = (size_t)PREP_WDN_BLKS * blockDim.x;
        }
        for (; i < n4; i += stride) {
            float4 v = src[i];
            dst[2 * i]     = __halves2half2(__float2half(v.x), __float2half(v.y));
            dst[2 * i + 1] = __halves2half2(__float2half(v.z), __float2half(v.w));
        }
    } else {
        b -= PREP_HID_BLKS + PREP_WGU_BLKS + PREP_WDN_BLKS;
        const size_t o4 = (size_t)NT * NH / 4;
        float4 z = make_float4(0.f, 0.f, 0.f, 0.f);
        size_t i = (size_t)b * blockDim.x + tid;
        size_t stride = (size_t)PREP_OUT_BLKS * blockDim.x;
        for (; i < o4; i += stride) out[i] = z;
    }
}

// ---------------- HMMA GEMMs ----------------
// M-tile 128 x N-tile 128, K-chunks of 64, 2 CTAs/SM, 3-stage cp.async
// pipeline with a single __syncthreads per chunk; prefetch issued right
// after the barrier (stage (c+2)%3 == (c-1)%3 was drained pre-barrier).
// Warps in 4x2 grid: warp tile 32 rows x 64 cols.
#define ROW_B   144
#define A_TB    (128 * ROW_B)               // 18432 B
#define B_TB    (128 * ROW_B)               // 18432 B
#define STAGE_B (A_TB + B_TB)               // 36864 B
#define NSTAGE  3
#define SMEM_TOT (NSTAGE * STAGE_B)         // 110592 B
#define OFF_A  0
#define OFF_B  A_TB
#define MAX_TILES 144

// ---- GEMM1: C[128 slots, 64 channels as gate|up pairs], K = NH ----
__global__ __launch_bounds__(256, 2) void k_gemm1() {
    extern __shared__ char smem[];
    const int ty = blockIdx.y;
    if (ty >= g_ntiles) return;
    const int e     = __ldg(&g_tile_e[ty]);
    const int m0    = __ldg(&g_tile_m0[ty]);
    const int start = __ldg(&g_offsets[e]);
    const int M     = __ldg(&g_offsets[e + 1]) - start;
    const int i0 = blockIdx.x * 64;     // gridDim.x = NI/64 = 22

    const int tid    = threadIdx.x;
    const int wid    = tid >> 5;
    const int lane   = tid & 31;
    const int warp_m = wid >> 1;        // 0..3
    const int warp_n = wid & 1;         // 0..1
    uint32_t sb = smem_u32(smem);

    const int vrow = tid >> 3;          // 0..31
    const int col8 = tid & 7;
    uint32_t arow[4], brow[4];
#pragma unroll
    for (int i = 0; i < 4; i++) {
        int row = vrow + 32 * i;        // 0..127
        int ar  = m0 + row; if (ar >= M) ar = M - 1;
        arow[i] = (uint32_t)__ldg(&g_slot_token[start + ar]) * NH;
        int half_ = row >> 6;
        int local = row & 63;
        int ch    = i0 + half_ * 32 + (local & 31);
        int role  = (local >> 5) & 1;
        brow[i] = (uint32_t)e * (2 * NI * NH) + (uint32_t)(ch + role * NI) * NH;
    }

    auto issue = [&](int s, int kk) {
        uint32_t base = sb + s * STAGE_B;
#pragma unroll
        for (int i = 0; i < 4; i++) {
            int row = vrow + 32 * i;
            uint32_t d = base + row * ROW_B + col8 * 16;
            CP_ASYNC16(d + OFF_A, g_hid_h + arow[i] + kk + col8 * 8);
            CP_ASYNC16(d + OFF_B, g_wgu_h + brow[i] + kk + col8 * 8);
        }
    };

    float acc[2][8][4];
#pragma unroll
    for (int mf = 0; mf < 2; mf++)
#pragma unroll
        for (int q = 0; q < 8; q++)
#pragma unroll
            for (int i = 0; i < 4; i++) acc[mf][q][i] = 0.f;

    const uint32_t a_base = (uint32_t)((warp_m * 32 + (lane & 15)) * ROW_B + (lane >> 4) * 16);
    const uint32_t b_base = (uint32_t)((warp_n * 64 + (lane & 7) + ((lane >> 4) & 1) * 8) * ROW_B +
                                       ((lane >> 3) & 1) * 16);

    issue(0, 0);   CP_COMMIT();
    issue(1, 64);  CP_COMMIT();

    const int NCH = NH / 64;
    for (int c = 0; c < NCH; c++) {
        if (c + 1 < NCH) CP_WAIT(1); else CP_WAIT(0);
        __syncthreads();
        if (c + 2 < NCH) { issue((c + 2) % NSTAGE, (c + 2) * 64); CP_COMMIT(); }
        uint32_t base = sb + (c % NSTAGE) * STAGE_B;
#pragma unroll
        for (int kk = 0; kk < 4; kk++) {
            uint32_t a0[4], a1[4];
            LDSM4(a0, base + OFF_A + a_base + kk * 32);
            LDSM4(a1, base + OFF_A + a_base + 16 * ROW_B + kk * 32);
#pragma unroll
            for (int nt = 0; nt < 4; nt++) {
                uint32_t bh[4];
                uint32_t bo = b_base + nt * (16 * ROW_B) + kk * 32;
                LDSM4(bh, base + OFF_B + bo);
                MMA16816(acc[0][2 * nt],     a0, bh[0], bh[1]);
                MMA16816(acc[0][2 * nt + 1], a0, bh[2], bh[3]);
                MMA16816(acc[1][2 * nt],     a1, bh[0], bh[1]);
                MMA16816(acc[1][2 * nt + 1], a1, bh[2], bh[3]);
            }
        }
    }

    // epilogue: acc[.][q] (q<4) = gate, acc[.][q+4] = up; h = silu(g)*u
    const int cb = (lane & 3) * 2;
#pragma unroll
    for (int mf = 0; mf < 2; mf++) {
        int rbase = m0 + warp_m * 32 + mf * 16 + (lane >> 2);
#pragma unroll
        for (int q = 0; q < 4; q++) {
            int ch = i0 + warp_n * 32 + q * 8 + cb;
#pragma unroll
            for (int half = 0; half < 2; half++) {
                int row = rbase + half * 8;
                if (row >= M) continue;
                float g0 = acc[mf][q][2 * half + 0],     g1 = acc[mf][q][2 * half + 1];
                float u0 = acc[mf][q + 4][2 * half + 0], u1 = acc[mf][q + 4][2 * half + 1];
                float h0 = u0 * g0 / (1.f + __expf(-g0));
                float h1 = u1 * g1 / (1.f + __expf(-g1));
                size_t o = (size_t)(start + row) * NI + ch;
                *(__half2*)(g_h_h + o) =
                    __halves2half2(__float2half(h0), __float2half(h1));
            }
        }
    }
}

// ---- GEMM2: C[128 slots, 128 hidden], K = NI; weighted atomic scatter ----
__global__ __launch_bounds__(256, 2) void k_gemm2(float* __restrict__ out) {
    extern __shared__ char smem[];
    const int ty = blockIdx.y;
    if (ty >= g_ntiles) return;
    const int e     = __ldg(&g_tile_e[ty]);
    const int m0    = __ldg(&g_tile_m0[ty]);
    const int start = __ldg(&g_offsets[e]);
    const int M     = __ldg(&g_offsets[e + 1]) - start;
    const int n0 = blockIdx.x * 128;    // gridDim.x = NH/128 = 16

    const int tid    = threadIdx.x;
    const int wid    = tid >> 5;
    const int lane   = tid & 31;
    const int warp_m = wid >> 1;
    const int warp_n = wid & 1;
    uint32_t sb = smem_u32(smem);

    const int vrow = tid >> 3;
    const int col8 = tid & 7;
    uint32_t arow[4], brow[4];
#pragma unroll
    for (int i = 0; i < 4; i++) {
        int row = vrow + 32 * i;
        int ar  = m0 + row; if (ar >= M) ar = M - 1;
        arow[i] = (uint32_t)(start + ar) * NI;
        brow[i] = (uint32_t)e * (NH * NI) + (uint32_t)(n0 + row) * NI;
    }

    auto issue = [&](int s, int kk) {
        uint32_t base = sb + s * STAGE_B;
#pragma unroll
        for (int i = 0; i < 4; i++) {
            int row = vrow + 32 * i;
            uint32_t d = base + row * ROW_B + col8 * 16;
            CP_ASYNC16(d + OFF_A, g_h_h   + arow[i] + kk + col8 * 8);
            CP_ASYNC16(d + OFF_B, g_wdn_h + brow[i] + kk + col8 * 8);
        }
    };

    float acc[2][8][4];
#pragma unroll
    for (int mf = 0; mf < 2; mf++)
#pragma unroll
        for (int q = 0; q < 8; q++)
#pragma unroll
            for (int i = 0; i < 4; i++) acc[mf][q][i] = 0.f;

    const uint32_t a_base = (uint32_t)((warp_m * 32 + (lane & 15)) * ROW_B + (lane >> 4) * 16);
    const uint32_t b_base = (uint32_t)((warp_n * 64 + (lane & 7) + ((lane >> 4) & 1) * 8) * ROW_B +
                                       ((lane >> 3) & 1) * 16);

    issue(0, 0);   CP_COMMIT();
    issue(1, 64);  CP_COMMIT();

    const int NCH = NI / 64;
    for (int c = 0; c < NCH; c++) {
        if (c + 1 < NCH) CP_WAIT(1); else CP_WAIT(0);
        __syncthreads();
        if (c + 2 < NCH) { issue((c + 2) % NSTAGE, (c + 2) * 64); CP_COMMIT(); }
        uint32_t base = sb + (c % NSTAGE) * STAGE_B;
#pragma unroll
        for (int kk = 0; kk < 4; kk++) {
            uint32_t a0[4], a1[4];
            LDSM4(a0, base + OFF_A + a_base + kk * 32);
            LDSM4(a1, base + OFF_A + a_base + 16 * ROW_B + kk * 32);
#pragma unroll
            for (int nt = 0; nt < 4; nt++) {
                uint32_t bh[4];
                uint32_t bo = b_base + nt * (16 * ROW_B) + kk * 32;
                LDSM4(bh, base + OFF_B + bo);
                MMA16816(acc[0][2 * nt],     a0, bh[0], bh[1]);
                MMA16816(acc[0][2 * nt + 1], a0, bh[2], bh[3]);
                MMA16816(acc[1][2 * nt],     a1, bh[0], bh[1]);
                MMA16816(acc[1][2 * nt + 1], a1, bh[2], bh[3]);
            }
        }
    }

    // epilogue: out[tok, n0 + warp_n*64 + col] += w * acc
    const int cb = (lane & 3) * 2;
#pragma unroll
    for (int mf = 0; mf < 2; mf++) {
        int rbase = m0 + warp_m * 32 + mf * 16 + (lane >> 2);
#pragma unroll
        for (int half = 0; half < 2; half++) {
            int row = rbase + half * 8;
            if (row >= M) continue;
            int   tok = __ldg(&g_slot_token[start + row]);
            float w   = __ldg(&g_slot_w[start + row]);
            float* orow = out + (size_t)tok * NH + n0 + warp_n * 64;
#pragma unroll
            for (int q = 0; q < 8; q++) {
                atomicAdd(orow + q * 8 + cb + 0, w * acc[mf][q][2 * half + 0]);
                atomicAdd(orow + q * 8 + cb + 1, w * acc[mf][q][2 * half + 1]);
            }
        }
    }
}

// ---------------- launch -----------------
extern "C" void kernel_launch(void* const* d_in, const int* in_sizes, int n_in,
                              void* d_out, int out_size) {
    const float* hidden = (const float*)d_in[0];   // [T, H]
    const void*  idx    = d_in[1];                 // [T, K] int32 or int64
    const float* wts    = (const float*)d_in[2];   // [T, K]
    const float* wgu    = (const float*)d_in[3];   // [E, 2I, H]
    const float* wdn    = (const float*)d_in[4];   // [E, H, I]
    (void)in_sizes; (void)n_in; (void)out_size;

    cudaFuncSetAttribute(k_gemm1, cudaFuncAttributeMaxDynamicSharedMemorySize, SMEM_TOT);
    cudaFuncSetAttribute(k_gemm2, cudaFuncAttributeMaxDynamicSharedMemorySize, SMEM_TOT);

    // prefix: routing + all fp16 conversions + output zero (one kernel)
    k_prep<<<PREP_BLKS, 256>>>((const float4*)hidden, (const int*)idx, wts,
                               (const float4*)wgu, (const float4*)wdn,
                               (float4*)d_out);

    // GEMM1: x = NI/64 = 22 tiles, y = compact tile list
    dim3 g1(NI / 64, MAX_TILES, 1);
    k_gemm1<<<g1, 256, SMEM_TOT>>>();

    // GEMM2: x = NH/128 = 16 tiles
    dim3 g2(NH / 128, MAX_TILES, 1);
    k_gemm2<<<g2, 256, SMEM_TOT>>>((float*)d_out);
}

// round 16
// speedup vs baseline: 2.0568x; 1.0932x over previous
#include <cuda_runtime.h>
#include <cuda_fp16.h>
#include <cstdint>

// Problem constants
#define NE 16
#define NH 2048
#define NI 1408
#define NK 2
#define NT 8192
#define CAP (NT * NK)   // 16384 routed slots

// ---------------- scratch (device globals; no cudaMalloc allowed) ----------
__device__ int   g_offsets[NE + 1];
__device__ int   g_slot_token[CAP];
__device__ float g_slot_w[CAP];
__device__ int   g_ntiles;
__device__ int   g_tile_e[160];
__device__ int   g_tile_m0[160];

// fp16 operands (round-to-nearest from fp32)
__device__ __align__(16) __half g_hid_h[(size_t)NT * NH];
__device__ __align__(16) __half g_wgu_h[(size_t)NE * 2 * NI * NH];
__device__ __align__(16) __half g_wdn_h[(size_t)NE * NH * NI];
__device__ __align__(16) __half g_h_h[(size_t)CAP * NI];

// ---------------- PTX helpers (baseline ISA only: sm_80+ features) ---------
__device__ __forceinline__ uint32_t smem_u32(const void* p) {
    uint32_t a;
    asm("{ .reg .u64 t; cvta.to.shared.u64 t, %1; cvt.u32.u64 %0, t; }" : "=r"(a) : "l"(p));
    return a;
}
#define CP_ASYNC16(dst, src) \
    asm volatile("cp.async.cg.shared.global [%0], [%1], 16;" :: "r"(dst), "l"(src))
#define CP_COMMIT() asm volatile("cp.async.commit_group;" ::: "memory")
#define CP_WAIT(N)  asm volatile("cp.async.wait_group %0;" :: "n"(N) : "memory")

#define LDSM4(r, addr) \
    asm volatile("ldmatrix.sync.aligned.m8n8.x4.shared.b16 {%0,%1,%2,%3}, [%4];" \
        : "=r"((r)[0]), "=r"((r)[1]), "=r"((r)[2]), "=r"((r)[3]) : "r"(addr))

#define MMA16816(c, a, b0_, b1_) \
    asm volatile("mma.sync.aligned.m16n8k16.row.col.f32.f16.f16.f32 " \
        "{%0,%1,%2,%3}, {%4,%5,%6,%7}, {%8,%9}, {%0,%1,%2,%3};" \
        : "+f"((c)[0]), "+f"((c)[1]), "+f"((c)[2]), "+f"((c)[3]) \
        : "r"((a)[0]), "r"((a)[1]), "r"((a)[2]), "r"((a)[3]), "r"(b0_), "r"(b1_))

// ---------------- prep: routing + all conversions + out zero, one kernel ---
#define PREP_HID_BLKS 2048
#define PREP_WGU_BLKS 8192
#define PREP_WDN_BLKS 4096
#define PREP_OUT_BLKS 1024
#define PREP_BLKS (1 + PREP_HID_BLKS + PREP_WGU_BLKS + PREP_WDN_BLKS + PREP_OUT_BLKS)

__global__ void k_prep(const float4* __restrict__ hidden,
                       const int*    __restrict__ idx32,
                       const float*  __restrict__ w,
                       const float4* __restrict__ wgu,
                       const float4* __restrict__ wdn,
                       float4*       __restrict__ out) {
    const int bid = blockIdx.x;
    const int tid = threadIdx.x;
    if (bid == 0) {
        // ---- routing ----
        __shared__ int cnt[NE], base_[NE], fill[NE];
        __shared__ int is64_s;
        if (tid < NE) { cnt[tid] = 0; fill[tid] = 0; }
        if (tid == 0) is64_s = 1;
        __syncthreads();
        // dtype detect: JAX x64-off silently downgrades int64->int32.
        if (tid < 256) {
            int lo = idx32[2 * tid], hi = idx32[2 * tid + 1];
            if (hi != 0 || lo < 0 || lo >= NE) atomicExch(&is64_s, 0);
        }
        __syncthreads();
        const int is64 = is64_s;
        for (int s = tid; s < CAP; s += blockDim.x) {
            int e = is64 ? (int)((const long long*)idx32)[s] : idx32[s];
            if (e >= 0 && e < NE) atomicAdd(&cnt[e], 1);
        }
        __syncthreads();
        if (tid == 0) {
            int acc = 0, nt = 0;
            for (int e = 0; e < NE; e++) {
                base_[e] = acc; g_offsets[e] = acc;
                for (int m0 = 0; m0 < cnt[e]; m0 += 128) {
                    g_tile_e[nt] = e; g_tile_m0[nt] = m0; nt++;
                }
                acc += cnt[e];
            }
            g_offsets[NE] = acc;
            g_ntiles = nt;
        }
        __syncthreads();
        for (int s = tid; s < CAP; s += blockDim.x) {
            int e = is64 ? (int)((const long long*)idx32)[s] : idx32[s];
            if (e >= 0 && e < NE) {
                int p = base_[e] + atomicAdd(&fill[e], 1);
                g_slot_token[p] = s / NK;
                g_slot_w[p]     = w[s];
            }
        }
        return;
    }
    int b = bid - 1;
    if (b < PREP_HID_BLKS + PREP_WGU_BLKS + PREP_WDN_BLKS) {
        const float4* src; __half2* dst; size_t n4, i, stride;
        if (b < PREP_HID_BLKS) {
            src = hidden; dst = (__half2*)g_hid_h;
            n4 = (size_t)NT * NH / 4;
            i = (size_t)b * blockDim.x + tid;
            stride = (size_t)PREP_HID_BLKS * blockDim.x;
        } else if (b < PREP_HID_BLKS + PREP_WGU_BLKS) {
            src = wgu; dst = (__half2*)g_wgu_h;
            n4 = (size_t)NE * 2 * NI * NH / 4;
            i = (size_t)(b - PREP_HID_BLKS) * blockDim.x + tid;
            stride = (size_t)PREP_WGU_BLKS * blockDim.x;
        } else {
            src = wdn; dst = (__half2*)g_wdn_h;
            n4 = (size_t)NE * NH * NI / 4;
            i = (size_t)(b - PREP_HID_BLKS - PREP_WGU_BLKS) * blockDim.x + tid;
            stride = (size_t)PREP_WDN_BLKS * blockDim.x;
        }
        for (; i < n4; i += stride) {
            float4 v = src[i];
            dst[2 * i]     = __halves2half2(__float2half(v.x), __float2half(v.y));
            dst[2 * i + 1] = __halves2half2(__float2half(v.z), __float2half(v.w));
        }
    } else {
        b -= PREP_HID_BLKS + PREP_WGU_BLKS + PREP_WDN_BLKS;
        const size_t o4 = (size_t)NT * NH / 4;
        float4 z = make_float4(0.f, 0.f, 0.f, 0.f);
        size_t i = (size_t)b * blockDim.x + tid;
        size_t stride = (size_t)PREP_OUT_BLKS * blockDim.x;
        for (; i < o4; i += stride) out[i] = z;
    }
}

// ---------------- HMMA GEMMs ----------------
// M-tile 128 x N-tile 128, K-chunks of 64, 2 CTAs/SM, 3-stage cp.async
// pipeline with a single __syncthreads per chunk; prefetch issued MID-chunk
// (after kk=1) — avoids the post-barrier LSU burst of top-issue while gaining
// half a chunk of prefetch depth over end-issue.
// Warps in 4x2 grid: warp tile 32 rows x 64 cols.
#define ROW_B   144
#define A_TB    (128 * ROW_B)               // 18432 B
#define B_TB    (128 * ROW_B)               // 18432 B
#define STAGE_B (A_TB + B_TB)               // 36864 B
#define NSTAGE  3
#define SMEM_TOT (NSTAGE * STAGE_B)         // 110592 B
#define OFF_A  0
#define OFF_B  A_TB
#define MAX_TILES 144

// ---- GEMM1: C[128 slots, 64 channels as gate|up pairs], K = NH ----
__global__ __launch_bounds__(256, 2) void k_gemm1() {
    extern __shared__ char smem[];
    const int ty = blockIdx.y;
    if (ty >= g_ntiles) return;
    const int e     = g_tile_e[ty];
    const int m0    = g_tile_m0[ty];
    const int start = g_offsets[e];
    const int M     = g_offsets[e + 1] - start;
    const int i0 = blockIdx.x * 64;     // gridDim.x = NI/64 = 22

    const int tid    = threadIdx.x;
    const int wid    = tid >> 5;
    const int lane   = tid & 31;
    const int warp_m = wid >> 1;        // 0..3
    const int warp_n = wid & 1;         // 0..1
    uint32_t sb = smem_u32(smem);

    const int vrow = tid >> 3;          // 0..31
    const int col8 = tid & 7;
    uint32_t arow[4], brow[4];
#pragma unroll
    for (int i = 0; i < 4; i++) {
        int row = vrow + 32 * i;        // 0..127
        int ar  = m0 + row; if (ar >= M) ar = M - 1;
        arow[i] = (uint32_t)g_slot_token[start + ar] * NH;
        int half_ = row >> 6;
        int local = row & 63;
        int ch    = i0 + half_ * 32 + (local & 31);
        int role  = (local >> 5) & 1;
        brow[i] = (uint32_t)e * (2 * NI * NH) + (uint32_t)(ch + role * NI) * NH;
    }

    auto issue = [&](int s, int kk) {
        uint32_t base = sb + s * STAGE_B;
#pragma unroll
        for (int i = 0; i < 4; i++) {
            int row = vrow + 32 * i;
            uint32_t d = base + row * ROW_B + col8 * 16;
            CP_ASYNC16(d + OFF_A, g_hid_h + arow[i] + kk + col8 * 8);
            CP_ASYNC16(d + OFF_B, g_wgu_h + brow[i] + kk + col8 * 8);
        }
    };

    float acc[2][8][4];
#pragma unroll
    for (int mf = 0; mf < 2; mf++)
#pragma unroll
        for (int q = 0; q < 8; q++)
#pragma unroll
            for (int i = 0; i < 4; i++) acc[mf][q][i] = 0.f;

    const uint32_t a_base = (uint32_t)((warp_m * 32 + (lane & 15)) * ROW_B + (lane >> 4) * 16);
    const uint32_t b_base = (uint32_t)((warp_n * 64 + (lane & 7) + ((lane >> 4) & 1) * 8) * ROW_B +
                                       ((lane >> 3) & 1) * 16);

    auto do_kk = [&](uint32_t base, int kk) {
        uint32_t a0[4], a1[4];
        LDSM4(a0, base + OFF_A + a_base + kk * 32);
        LDSM4(a1, base + OFF_A + a_base + 16 * ROW_B + kk * 32);
#pragma unroll
        for (int nt = 0; nt < 4; nt++) {
            uint32_t bh[4];
            uint32_t bo = b_base + nt * (16 * ROW_B) + kk * 32;
            LDSM4(bh, base + OFF_B + bo);
            MMA16816(acc[0][2 * nt],     a0, bh[0], bh[1]);
            MMA16816(acc[0][2 * nt + 1], a0, bh[2], bh[3]);
            MMA16816(acc[1][2 * nt],     a1, bh[0], bh[1]);
            MMA16816(acc[1][2 * nt + 1], a1, bh[2], bh[3]);
        }
    };

    issue(0, 0);   CP_COMMIT();
    issue(1, 64);  CP_COMMIT();

    const int NCH = NH / 64;
    for (int c = 0; c < NCH; c++) {
        if (c + 1 < NCH) CP_WAIT(1); else CP_WAIT(0);
        __syncthreads();
        uint32_t base = sb + (c % NSTAGE) * STAGE_B;
        do_kk(base, 0);
        do_kk(base, 1);
        if (c + 2 < NCH) { issue((c + 2) % NSTAGE, (c + 2) * 64); CP_COMMIT(); }
        do_kk(base, 2);
        do_kk(base, 3);
    }

    // epilogue: acc[.][q] (q<4) = gate, acc[.][q+4] = up; h = silu(g)*u
    const int cb = (lane & 3) * 2;
#pragma unroll
    for (int mf = 0; mf < 2; mf++) {
        int rbase = m0 + warp_m * 32 + mf * 16 + (lane >> 2);
#pragma unroll
        for (int q = 0; q < 4; q++) {
            int ch = i0 + warp_n * 32 + q * 8 + cb;
#pragma unroll
            for (int half = 0; half < 2; half++) {
                int row = rbase + half * 8;
                if (row >= M) continue;
                float g0 = acc[mf][q][2 * half + 0],     g1 = acc[mf][q][2 * half + 1];
                float u0 = acc[mf][q + 4][2 * half + 0], u1 = acc[mf][q + 4][2 * half + 1];
                float h0 = u0 * g0 / (1.f + __expf(-g0));
                float h1 = u1 * g1 / (1.f + __expf(-g1));
                size_t o = (size_t)(start + row) * NI + ch;
                *(__half2*)(g_h_h + o) =
                    __halves2half2(__float2half(h0), __float2half(h1));
            }
        }
    }
}

// ---- GEMM2: C[128 slots, 128 hidden], K = NI; weighted atomic scatter ----
__global__ __launch_bounds__(256, 2) void k_gemm2(float* __restrict__ out) {
    extern __shared__ char smem[];
    const int ty = blockIdx.y;
    if (ty >= g_ntiles) return;
    const int e     = g_tile_e[ty];
    const int m0    = g_tile_m0[ty];
    const int start = g_offsets[e];
    const int M     = g_offsets[e + 1] - start;
    const int n0 = blockIdx.x * 128;    // gridDim.x = NH/128 = 16

    const int tid    = threadIdx.x;
    const int wid    = tid >> 5;
    const int lane   = tid & 31;
    const int warp_m = wid >> 1;
    const int warp_n = wid & 1;
    uint32_t sb = smem_u32(smem);

    const int vrow = tid >> 3;
    const int col8 = tid & 7;
    uint32_t arow[4], brow[4];
#pragma unroll
    for (int i = 0; i < 4; i++) {
        int row = vrow + 32 * i;
        int ar  = m0 + row; if (ar >= M) ar = M - 1;
        arow[i] = (uint32_t)(start + ar) * NI;
        brow[i] = (uint32_t)e * (NH * NI) + (uint32_t)(n0 + row) * NI;
    }

    auto issue = [&](int s, int kk) {
        uint32_t base = sb + s * STAGE_B;
#pragma unroll
        for (int i = 0; i < 4; i++) {
            int row = vrow + 32 * i;
            uint32_t d = base + row * ROW_B + col8 * 16;
            CP_ASYNC16(d + OFF_A, g_h_h   + arow[i] + kk + col8 * 8);
            CP_ASYNC16(d + OFF_B, g_wdn_h + brow[i] + kk + col8 * 8);
        }
    };

    float acc[2][8][4];
#pragma unroll
    for (int mf = 0; mf < 2; mf++)
#pragma unroll
        for (int q = 0; q < 8; q++)
#pragma unroll
            for (int i = 0; i < 4; i++) acc[mf][q][i] = 0.f;

    const uint32_t a_base = (uint32_t)((warp_m * 32 + (lane & 15)) * ROW_B + (lane >> 4) * 16);
    const uint32_t b_base = (uint32_t)((warp_n * 64 + (lane & 7) + ((lane >> 4) & 1) * 8) * ROW_B +
                                       ((lane >> 3) & 1) * 16);

    auto do_kk = [&](uint32_t base, int kk) {
        uint32_t a0[4], a1[4];
        LDSM4(a0, base + OFF_A + a_base + kk * 32);
        LDSM4(a1, base + OFF_A + a_base + 16 * ROW_B + kk * 32);
#pragma unroll
        for (int nt = 0; nt < 4; nt++) {
            uint32_t bh[4];
            uint32_t bo = b_base + nt * (16 * ROW_B) + kk * 32;
            LDSM4(bh, base + OFF_B + bo);
            MMA16816(acc[0][2 * nt],     a0, bh[0], bh[1]);
            MMA16816(acc[0][2 * nt + 1], a0, bh[2], bh[3]);
            MMA16816(acc[1][2 * nt],     a1, bh[0], bh[1]);
            MMA16816(acc[1][2 * nt + 1], a1, bh[2], bh[3]);
        }
    };

    issue(0, 0);   CP_COMMIT();
    issue(1, 64);  CP_COMMIT();

    const int NCH = NI / 64;
    for (int c = 0; c < NCH; c++) {
        if (c + 1 < NCH) CP_WAIT(1); else CP_WAIT(0);
        __syncthreads();
        uint32_t base = sb + (c % NSTAGE) * STAGE_B;
        do_kk(base, 0);
        do_kk(base, 1);
        if (c + 2 < NCH) { issue((c + 2) % NSTAGE, (c + 2) * 64); CP_COMMIT(); }
        do_kk(base, 2);
        do_kk(base, 3);
    }

    // epilogue: out[tok, n0 + warp_n*64 + col] += w * acc
    const int cb = (lane & 3) * 2;
#pragma unroll
    for (int mf = 0; mf < 2; mf++) {
        int rbase = m0 + warp_m * 32 + mf * 16 + (lane >> 2);
#pragma unroll
        for (int half = 0; half < 2; half++) {
            int row = rbase + half * 8;
            if (row >= M) continue;
            int   tok = g_slot_token[start + row];
            float w   = g_slot_w[start + row];
            float* orow = out + (size_t)tok * NH + n0 + warp_n * 64;
#pragma unroll
            for (int q = 0; q < 8; q++) {
                atomicAdd(orow + q * 8 + cb + 0, w * acc[mf][q][2 * half + 0]);
                atomicAdd(orow + q * 8 + cb + 1, w * acc[mf][q][2 * half + 1]);
            }
        }
    }
}

// ---------------- launch -----------------
extern "C" void kernel_launch(void* const* d_in, const int* in_sizes, int n_in,
                              void* d_out, int out_size) {
    const float* hidden = (const float*)d_in[0];   // [T, H]
    const void*  idx    = d_in[1];                 // [T, K] int32 or int64
    const float* wts    = (const float*)d_in[2];   // [T, K]
    const float* wgu    = (const float*)d_in[3];   // [E, 2I, H]
    const float* wdn    = (const float*)d_in[4];   // [E, H, I]
    (void)in_sizes; (void)n_in; (void)out_size;

    cudaFuncSetAttribute(k_gemm1, cudaFuncAttributeMaxDynamicSharedMemorySize, SMEM_TOT);
    cudaFuncSetAttribute(k_gemm2, cudaFuncAttributeMaxDynamicSharedMemorySize, SMEM_TOT);

    // prefix: routing + all fp16 conversions + output zero (one kernel)
    k_prep<<<PREP_BLKS, 256>>>((const float4*)hidden, (const int*)idx, wts,
                               (const float4*)wgu, (const float4*)wdn,
                               (float4*)d_out);

    // GEMM1: x = NI/64 = 22 tiles, y = compact tile list
    dim3 g1(NI / 64, MAX_TILES, 1);
    k_gemm1<<<g1, 256, SMEM_TOT>>>();

    // GEMM2: x = NH/128 = 16 tiles
    dim3 g2(NH / 128, MAX_TILES, 1);
    k_gemm2<<<g2, 256, SMEM_TOT>>>((float*)d_out);
}

// round 17
// speedup vs baseline: 2.1883x; 1.0639x over previous
#include <cuda_runtime.h>
#include <cuda_fp16.h>
#include <cstdint>

// Problem constants
#define NE 16
#define NH 2048
#define NI 1408
#define NK 2
#define NT 8192
#define CAP (NT * NK)   // 16384 routed slots

// ---------------- scratch (device globals; no cudaMalloc allowed) ----------
__device__ int   g_offsets[NE + 1];
__device__ int   g_slot_token[CAP];
__device__ float g_slot_w[CAP];
__device__ int   g_ntiles;
__device__ int   g_tile_e[160];
__device__ int   g_tile_m0[160];

// fp16 operands (round-to-nearest from fp32)
__device__ __align__(16) __half g_hid_h[(size_t)NT * NH];
__device__ __align__(16) __half g_wgu_h[(size_t)NE * 2 * NI * NH];
__device__ __align__(16) __half g_wdn_h[(size_t)NE * NH * NI];
__device__ __align__(16) __half g_h_h[(size_t)CAP * NI];

// ---------------- PTX helpers (baseline ISA only: sm_80+ features) ---------
__device__ __forceinline__ uint32_t smem_u32(const void* p) {
    uint32_t a;
    asm("{ .reg .u64 t; cvta.to.shared.u64 t, %1; cvt.u32.u64 %0, t; }" : "=r"(a) : "l"(p));
    return a;
}
#define CP_ASYNC16(dst, src) \
    asm volatile("cp.async.cg.shared.global [%0], [%1], 16;" :: "r"(dst), "l"(src))
#define CP_COMMIT() asm volatile("cp.async.commit_group;" ::: "memory")
#define CP_WAIT(N)  asm volatile("cp.async.wait_group %0;" :: "n"(N) : "memory")

#define LDSM4(r, addr) \
    asm volatile("ldmatrix.sync.aligned.m8n8.x4.shared.b16 {%0,%1,%2,%3}, [%4];" \
        : "=r"((r)[0]), "=r"((r)[1]), "=r"((r)[2]), "=r"((r)[3]) : "r"(addr))

#define MMA16816(c, a, b0_, b1_) \
    asm volatile("mma.sync.aligned.m16n8k16.row.col.f32.f16.f16.f32 " \
        "{%0,%1,%2,%3}, {%4,%5,%6,%7}, {%8,%9}, {%0,%1,%2,%3};" \
        : "+f"((c)[0]), "+f"((c)[1]), "+f"((c)[2]), "+f"((c)[3]) \
        : "r"((a)[0]), "r"((a)[1]), "r"((a)[2]), "r"((a)[3]), "r"(b0_), "r"(b1_))

// ---------------- prep: routing + all conversions + out zero, one kernel ---
#define PREP_HID_BLKS 2048
#define PREP_WGU_BLKS 8192
#define PREP_WDN_BLKS 4096
#define PREP_OUT_BLKS 1024
#define PREP_BLKS (1 + PREP_HID_BLKS + PREP_WGU_BLKS + PREP_WDN_BLKS + PREP_OUT_BLKS)

__global__ void k_prep(const float4* __restrict__ hidden,
                       const int*    __restrict__ idx32,
                       const float*  __restrict__ w,
                       const float4* __restrict__ wgu,
                       const float4* __restrict__ wdn,
                       float4*       __restrict__ out) {
    const int bid = blockIdx.x;
    const int tid = threadIdx.x;
    if (bid == 0) {
        // ---- routing ----
        __shared__ int cnt[NE], base_[NE], fill[NE];
        __shared__ int is64_s;
        if (tid < NE) { cnt[tid] = 0; fill[tid] = 0; }
        if (tid == 0) is64_s = 1;
        __syncthreads();
        // dtype detect: JAX x64-off silently downgrades int64->int32.
        if (tid < 256) {
            int lo = idx32[2 * tid], hi = idx32[2 * tid + 1];
            if (hi != 0 || lo < 0 || lo >= NE) atomicExch(&is64_s, 0);
        }
        __syncthreads();
        const int is64 = is64_s;
        for (int s = tid; s < CAP; s += blockDim.x) {
            int e = is64 ? (int)((const long long*)idx32)[s] : idx32[s];
            if (e >= 0 && e < NE) atomicAdd(&cnt[e], 1);
        }
        __syncthreads();
        if (tid == 0) {
            int acc = 0, nt = 0;
            for (int e = 0; e < NE; e++) {
                base_[e] = acc; g_offsets[e] = acc;
                for (int m0 = 0; m0 < cnt[e]; m0 += 128) {
                    g_tile_e[nt] = e; g_tile_m0[nt] = m0; nt++;
                }
                acc += cnt[e];
            }
            g_offsets[NE] = acc;
            g_ntiles = nt;
        }
        __syncthreads();
        for (int s = tid; s < CAP; s += blockDim.x) {
            int e = is64 ? (int)((const long long*)idx32)[s] : idx32[s];
            if (e >= 0 && e < NE) {
                int p = base_[e] + atomicAdd(&fill[e], 1);
                g_slot_token[p] = s / NK;
                g_slot_w[p]     = w[s];
            }
        }
        return;
    }
    int b = bid - 1;
    if (b < PREP_HID_BLKS + PREP_WGU_BLKS + PREP_WDN_BLKS) {
        const float4* src; __half2* dst; size_t n4, i, stride;
        if (b < PREP_HID_BLKS) {
            src = hidden; dst = (__half2*)g_hid_h;
            n4 = (size_t)NT * NH / 4;
            i = (size_t)b * blockDim.x + tid;
            stride = (size_t)PREP_HID_BLKS * blockDim.x;
        } else if (b < PREP_HID_BLKS + PREP_WGU_BLKS) {
            src = wgu; dst = (__half2*)g_wgu_h;
            n4 = (size_t)NE * 2 * NI * NH / 4;
            i = (size_t)(b - PREP_HID_BLKS) * blockDim.x + tid;
            stride = (size_t)PREP_WGU_BLKS * blockDim.x;
        } else {
            src = wdn; dst = (__half2*)g_wdn_h;
            n4 = (size_t)NE * NH * NI / 4;
            i = (size_t)(b - PREP_HID_BLKS - PREP_WGU_BLKS) * blockDim.x + tid;
            stride = (size_t)PREP_WDN_BLKS * blockDim.x;
        }
        for (; i < n4; i += stride) {
            float4 v = src[i];
            dst[2 * i]     = __halves2half2(__float2half(v.x), __float2half(v.y));
            dst[2 * i + 1] = __halves2half2(__float2half(v.z), __float2half(v.w));
        }
    } else {
        b -= PREP_HID_BLKS + PREP_WGU_BLKS + PREP_WDN_BLKS;
        const size_t o4 = (size_t)NT * NH / 4;
        float4 z = make_float4(0.f, 0.f, 0.f, 0.f);
        size_t i = (size_t)b * blockDim.x + tid;
        size_t stride = (size_t)PREP_OUT_BLKS * blockDim.x;
        for (; i < o4; i += stride) out[i] = z;
    }
}

// ---------------- HMMA GEMMs ----------------
// M-tile 128 x N-tile 128, K-chunks of 64, 2 CTAs/SM, 3-stage cp.async
// pipeline, single __syncthreads per chunk. Prefetch issued as TWO groups
// per stage (A-half after kk=0, B-half after kk=2) to spread LSU issue;
// every stage = 2 groups -> uniform CP_WAIT(2) at chunk top.
// Warps in 4x2 grid: warp tile 32 rows x 64 cols.
#define ROW_B   144
#define A_TB    (128 * ROW_B)               // 18432 B
#define B_TB    (128 * ROW_B)               // 18432 B
#define STAGE_B (A_TB + B_TB)               // 36864 B
#define NSTAGE  3
#define SMEM_TOT (NSTAGE * STAGE_B)         // 110592 B
#define OFF_A  0
#define OFF_B  A_TB
#define MAX_TILES 144

// ---- GEMM1: C[128 slots, 64 channels as gate|up pairs], K = NH ----
__global__ __launch_bounds__(256, 2) void k_gemm1() {
    extern __shared__ char smem[];
    const int ty = blockIdx.y;
    if (ty >= g_ntiles) return;
    const int e     = g_tile_e[ty];
    const int m0    = g_tile_m0[ty];
    const int start = g_offsets[e];
    const int M     = g_offsets[e + 1] - start;
    const int i0 = blockIdx.x * 64;     // gridDim.x = NI/64 = 22

    const int tid    = threadIdx.x;
    const int wid    = tid >> 5;
    const int lane   = tid & 31;
    const int warp_m = wid >> 1;        // 0..3
    const int warp_n = wid & 1;         // 0..1
    uint32_t sb = smem_u32(smem);

    const int vrow = tid >> 3;          // 0..31
    const int col8 = tid & 7;
    uint32_t arow[4], brow[4];
#pragma unroll
    for (int i = 0; i < 4; i++) {
        int row = vrow + 32 * i;        // 0..127
        int ar  = m0 + row; if (ar >= M) ar = M - 1;
        arow[i] = (uint32_t)g_slot_token[start + ar] * NH;
        int half_ = row >> 6;
        int local = row & 63;
        int ch    = i0 + half_ * 32 + (local & 31);
        int role  = (local >> 5) & 1;
        brow[i] = (uint32_t)e * (2 * NI * NH) + (uint32_t)(ch + role * NI) * NH;
    }

    auto issueA = [&](int s, int kk) {
        uint32_t base = sb + s * STAGE_B;
#pragma unroll
        for (int i = 0; i < 4; i++) {
            int row = vrow + 32 * i;
            uint32_t d = base + row * ROW_B + col8 * 16;
            CP_ASYNC16(d + OFF_A, g_hid_h + arow[i] + kk + col8 * 8);
        }
    };
    auto issueB = [&](int s, int kk) {
        uint32_t base = sb + s * STAGE_B;
#pragma unroll
        for (int i = 0; i < 4; i++) {
            int row = vrow + 32 * i;
            uint32_t d = base + row * ROW_B + col8 * 16;
            CP_ASYNC16(d + OFF_B, g_wgu_h + brow[i] + kk + col8 * 8);
        }
    };

    float acc[2][8][4];
#pragma unroll
    for (int mf = 0; mf < 2; mf++)
#pragma unroll
        for (int q = 0; q < 8; q++)
#pragma unroll
            for (int i = 0; i < 4; i++) acc[mf][q][i] = 0.f;

    const uint32_t a_base = (uint32_t)((warp_m * 32 + (lane & 15)) * ROW_B + (lane >> 4) * 16);
    const uint32_t b_base = (uint32_t)((warp_n * 64 + (lane & 7) + ((lane >> 4) & 1) * 8) * ROW_B +
                                       ((lane >> 3) & 1) * 16);

    auto do_kk = [&](uint32_t base, int kk) {
        uint32_t a0[4], a1[4];
        LDSM4(a0, base + OFF_A + a_base + kk * 32);
        LDSM4(a1, base + OFF_A + a_base + 16 * ROW_B + kk * 32);
#pragma unroll
        for (int nt = 0; nt < 4; nt++) {
            uint32_t bh[4];
            uint32_t bo = b_base + nt * (16 * ROW_B) + kk * 32;
            LDSM4(bh, base + OFF_B + bo);
            MMA16816(acc[0][2 * nt],     a0, bh[0], bh[1]);
            MMA16816(acc[0][2 * nt + 1], a0, bh[2], bh[3]);
            MMA16816(acc[1][2 * nt],     a1, bh[0], bh[1]);
            MMA16816(acc[1][2 * nt + 1], a1, bh[2], bh[3]);
        }
    };

    // prologue: each stage committed as 2 groups (A, B) for uniform WAIT(2)
    issueA(0, 0);  CP_COMMIT();
    issueB(0, 0);  CP_COMMIT();
    issueA(1, 64); CP_COMMIT();
    issueB(1, 64); CP_COMMIT();

    const int NCH = NH / 64;
    for (int c = 0; c < NCH; c++) {
        if (c + 1 < NCH) CP_WAIT(2); else CP_WAIT(0);
        __syncthreads();
        uint32_t base = sb + (c % NSTAGE) * STAGE_B;
        const bool pf = (c + 2 < NCH);
        const int  s2 = (c + 2) % NSTAGE;
        const int  k2 = (c + 2) * 64;
        do_kk(base, 0);
        if (pf) { issueA(s2, k2); CP_COMMIT(); }
        do_kk(base, 1);
        do_kk(base, 2);
        if (pf) { issueB(s2, k2); CP_COMMIT(); }
        do_kk(base, 3);
    }

    // epilogue: acc[.][q] (q<4) = gate, acc[.][q+4] = up; h = silu(g)*u
    const int cb = (lane & 3) * 2;
#pragma unroll
    for (int mf = 0; mf < 2; mf++) {
        int rbase = m0 + warp_m * 32 + mf * 16 + (lane >> 2);
#pragma unroll
        for (int q = 0; q < 4; q++) {
            int ch = i0 + warp_n * 32 + q * 8 + cb;
#pragma unroll
            for (int half = 0; half < 2; half++) {
                int row = rbase + half * 8;
                if (row >= M) continue;
                float g0 = acc[mf][q][2 * half + 0],     g1 = acc[mf][q][2 * half + 1];
                float u0 = acc[mf][q + 4][2 * half + 0], u1 = acc[mf][q + 4][2 * half + 1];
                float h0 = u0 * g0 / (1.f + __expf(-g0));
                float h1 = u1 * g1 / (1.f + __expf(-g1));
                size_t o = (size_t)(start + row) * NI + ch;
                *(__half2*)(g_h_h + o) =
                    __halves2half2(__float2half(h0), __float2half(h1));
            }
        }
    }
}

// ---- GEMM2: C[128 slots, 128 hidden], K = NI; weighted atomic scatter ----
__global__ __launch_bounds__(256, 2) void k_gemm2(float* __restrict__ out) {
    extern __shared__ char smem[];
    const int ty = blockIdx.y;
    if (ty >= g_ntiles) return;
    const int e     = g_tile_e[ty];
    const int m0    = g_tile_m0[ty];
    const int start = g_offsets[e];
    const int M     = g_offsets[e + 1] - start;
    const int n0 = blockIdx.x * 128;    // gridDim.x = NH/128 = 16

    const int tid    = threadIdx.x;
    const int wid    = tid >> 5;
    const int lane   = tid & 31;
    const int warp_m = wid >> 1;
    const int warp_n = wid & 1;
    uint32_t sb = smem_u32(smem);

    const int vrow = tid >> 3;
    const int col8 = tid & 7;
    uint32_t arow[4], brow[4];
#pragma unroll
    for (int i = 0; i < 4; i++) {
        int row = vrow + 32 * i;
        int ar  = m0 + row; if (ar >= M) ar = M - 1;
        arow[i] = (uint32_t)(start + ar) * NI;
        brow[i] = (uint32_t)e * (NH * NI) + (uint32_t)(n0 + row) * NI;
    }

    auto issueA = [&](int s, int kk) {
        uint32_t base = sb + s * STAGE_B;
#pragma unroll
        for (int i = 0; i < 4; i++) {
            int row = vrow + 32 * i;
            uint32_t d = base + row * ROW_B + col8 * 16;
            CP_ASYNC16(d + OFF_A, g_h_h + arow[i] + kk + col8 * 8);
        }
    };
    auto issueB = [&](int s, int kk) {
        uint32_t base = sb + s * STAGE_B;
#pragma unroll
        for (int i = 0; i < 4; i++) {
            int row = vrow + 32 * i;
            uint32_t d = base + row * ROW_B + col8 * 16;
            CP_ASYNC16(d + OFF_B, g_wdn_h + brow[i] + kk + col8 * 8);
        }
    };

    float acc[2][8][4];
#pragma unroll
    for (int mf = 0; mf < 2; mf++)
#pragma unroll
        for (int q = 0; q < 8; q++)
#pragma unroll
            for (int i = 0; i < 4; i++) acc[mf][q][i] = 0.f;

    const uint32_t a_base = (uint32_t)((warp_m * 32 + (lane & 15)) * ROW_B + (lane >> 4) * 16);
    const uint32_t b_base = (uint32_t)((warp_n * 64 + (lane & 7) + ((lane >> 4) & 1) * 8) * ROW_B +
                                       ((lane >> 3) & 1) * 16);

    auto do_kk = [&](uint32_t base, int kk) {
        uint32_t a0[4], a1[4];
        LDSM4(a0, base + OFF_A + a_base + kk * 32);
        LDSM4(a1, base + OFF_A + a_base + 16 * ROW_B + kk * 32);
#pragma unroll
        for (int nt = 0; nt < 4; nt++) {
            uint32_t bh[4];
            uint32_t bo = b_base + nt * (16 * ROW_B) + kk * 32;
            LDSM4(bh, base + OFF_B + bo);
            MMA16816(acc[0][2 * nt],     a0, bh[0], bh[1]);
            MMA16816(acc[0][2 * nt + 1], a0, bh[2], bh[3]);
            MMA16816(acc[1][2 * nt],     a1, bh[0], bh[1]);
            MMA16816(acc[1][2 * nt + 1], a1, bh[2], bh[3]);
        }
    };

    issueA(0, 0);  CP_COMMIT();
    issueB(0, 0);  CP_COMMIT();
    issueA(1, 64); CP_COMMIT();
    issueB(1, 64); CP_COMMIT();

    const int NCH = NI / 64;
    for (int c = 0; c < NCH; c++) {
        if (c + 1 < NCH) CP_WAIT(2); else CP_WAIT(0);
        __syncthreads();
        uint32_t base = sb + (c % NSTAGE) * STAGE_B;
        const bool pf = (c + 2 < NCH);
        const int  s2 = (c + 2) % NSTAGE;
        const int  k2 = (c + 2) * 64;
        do_kk(base, 0);
        if (pf) { issueA(s2, k2); CP_COMMIT(); }
        do_kk(base, 1);
        do_kk(base, 2);
        if (pf) { issueB(s2, k2); CP_COMMIT(); }
        do_kk(base, 3);
    }

    // epilogue: out[tok, n0 + warp_n*64 + col] += w * acc
    const int cb = (lane & 3) * 2;
#pragma unroll
    for (int mf = 0; mf < 2; mf++) {
        int rbase = m0 + warp_m * 32 + mf * 16 + (lane >> 2);
#pragma unroll
        for (int half = 0; half < 2; half++) {
            int row = rbase + half * 8;
            if (row >= M) continue;
            int   tok = g_slot_token[start + row];
            float w   = g_slot_w[start + row];
            float* orow = out + (size_t)tok * NH + n0 + warp_n * 64;
#pragma unroll
            for (int q = 0; q < 8; q++) {
                atomicAdd(orow + q * 8 + cb + 0, w * acc[mf][q][2 * half + 0]);
                atomicAdd(orow + q * 8 + cb + 1, w * acc[mf][q][2 * half + 1]);
            }
        }
    }
}

// ---------------- launch -----------------
extern "C" void kernel_launch(void* const* d_in, const int* in_sizes, int n_in,
                              void* d_out, int out_size) {
    const float* hidden = (const float*)d_in[0];   // [T, H]
    const void*  idx    = d_in[1];                 // [T, K] int32 or int64
    const float* wts    = (const float*)d_in[2];   // [T, K]
    const float* wgu    = (const float*)d_in[3];   // [E, 2I, H]
    const float* wdn    = (const float*)d_in[4];   // [E, H, I]
    (void)in_sizes; (void)n_in; (void)out_size;

    cudaFuncSetAttribute(k_gemm1, cudaFuncAttributeMaxDynamicSharedMemorySize, SMEM_TOT);
    cudaFuncSetAttribute(k_gemm2, cudaFuncAttributeMaxDynamicSharedMemorySize, SMEM_TOT);

    // prefix: routing + all fp16 conversions + output zero (one kernel)
    k_prep<<<PREP_BLKS, 256>>>((const float4*)hidden, (const int*)idx, wts,
                               (const float4*)wgu, (const float4*)wdn,
                               (float4*)d_out);

    // GEMM1: x = NI/64 = 22 tiles, y = compact tile list
    dim3 g1(NI / 64, MAX_TILES, 1);
    k_gemm1<<<g1, 256, SMEM_TOT>>>();

    // GEMM2: x = NH/128 = 16 tiles
    dim3 g2(NH / 128, MAX_TILES, 1);
    k_gemm2<<<g2, 256, SMEM_TOT>>>((float*)d_out);
}